// round 2
// baseline (speedup 1.0000x reference)
#include <cuda_runtime.h>

#define E_    4096
#define NN_   2048
#define D_    256
#define H_    8
#define DH_   32
#define NEG_  (-10000.0f)

// ---------------- scratch (device globals; no allocation allowed) ----------
__device__ float g_cat [E_ * 3 * D_];
__device__ float g_h1  [E_ * D_];
__device__ float g_h   [E_ * D_];
__device__ float g_qkv [E_ * 3 * D_];
__device__ float g_o   [E_ * D_];
__device__ float g_msg [E_ * D_];
__device__ float g_node[NN_ * D_];
__device__ float g_y   [NN_ * D_];
__device__ float g_z   [NN_ * D_];
__device__ unsigned char g_mask[(size_t)E_ * E_];   // canonical u8 mask

// ---------------- mask canonicalization ------------------------------------
// The reference passes a jax bool array; the harness transports it as an
// unknown concrete dtype (u8 / int32 / float32 / bf16). Detect the format by
// bit-pattern voting over the first 64 words (density 0.95 makes the true
// format's signature word dominate), then convert to a canonical 0/1 byte
// mask. Deterministic: depends only on input data.
__global__ void mask_convert_kernel(const unsigned int* __restrict__ mw,
                                    unsigned char* __restrict__ mb) {
    __shared__ int cnt[4];
    if (threadIdx.x < 4) cnt[threadIdx.x] = 0;
    __syncthreads();
    if (threadIdx.x < 64) {
        unsigned int w = mw[threadIdx.x];
        if      (w == 0x01010101u) atomicAdd(&cnt[0], 1);  // u8 bool
        else if (w == 0x3F800000u) atomicAdd(&cnt[1], 1);  // float32
        else if (w == 0x00000001u) atomicAdd(&cnt[2], 1);  // int32
        else if (w == 0x3F803F80u) atomicAdd(&cnt[3], 1);  // bf16
    }
    __syncthreads();
    int fmt = 0, best = cnt[0];
    if (cnt[1] > best) { best = cnt[1]; fmt = 1; }
    if (cnt[2] > best) { best = cnt[2]; fmt = 2; }
    if (cnt[3] > best) { best = cnt[3]; fmt = 3; }

    size_t idx = ((size_t)blockIdx.x * blockDim.x + threadIdx.x) * 4;
    uchar4 outv;
    if (fmt == 0) {
        uchar4 v = *(const uchar4*)((const unsigned char*)mw + idx);
        outv = make_uchar4(v.x != 0, v.y != 0, v.z != 0, v.w != 0);
    } else if (fmt == 1 || fmt == 2) {
        uint4 v = *(const uint4*)(mw + idx);   // 0/1 as int or 0.0/1.0 as float bits
        outv = make_uchar4(v.x != 0, v.y != 0, v.z != 0, v.w != 0);
    } else {
        const unsigned short* ms = (const unsigned short*)mw;
        outv = make_uchar4(ms[idx] != 0, ms[idx + 1] != 0,
                           ms[idx + 2] != 0, ms[idx + 3] != 0);
    }
    *(uchar4*)&mb[idx] = outv;
}

// ---------------- gather: cat = [x_i, x_j, edge_attr] ----------------------
__global__ void gather_cat_kernel(const float* __restrict__ x,
                                  const int* __restrict__ ei,
                                  const float* __restrict__ ea,
                                  float* __restrict__ cat) {
    int e = blockIdx.x;
    int d = threadIdx.x;
    int src = ei[e];        // edge_index[0] = x_j (source)
    int tgt = ei[E_ + e];   // edge_index[1] = x_i (target)
    cat[(size_t)e * 768 + d]         = x[(size_t)tgt * 256 + d];
    cat[(size_t)e * 768 + 256 + d]   = x[(size_t)src * 256 + d];
    cat[(size_t)e * 768 + 512 + d]   = ea[(size_t)e * 256 + d];
}

// ---------------- generic tiled SGEMM --------------------------------------
// C[M,N] = A[M,K] @ op(B) + bias ;  BT: B stored [N,K] (compute A@B^T)
//                                  !BT: B stored [K,N] (compute A@B)
// BM=BN=64, BK=16, 256 threads, 4x4 microtile per thread.
template <bool BT, bool LRELU>
__global__ void sgemm_kernel(const float* __restrict__ A,
                             const float* __restrict__ B,
                             const float* __restrict__ bias,
                             float* __restrict__ C,
                             int M, int N, int K) {
    __shared__ float As[16 * 64];
    __shared__ float Bs[16 * 64];

    int tid = threadIdx.x;
    int tx = tid & 15;          // 0..15 -> output cols (4 each)
    int ty = tid >> 4;          // 0..15 -> output rows (4 each)
    int row0 = blockIdx.y * 64;
    int col0 = blockIdx.x * 64;

    float acc[4][4];
#pragma unroll
    for (int i = 0; i < 4; i++)
#pragma unroll
        for (int j = 0; j < 4; j++) acc[i][j] = 0.0f;

    for (int k0 = 0; k0 < K; k0 += 16) {
        {
            int ar = tid >> 2;
            int ac = (tid & 3) * 4;
            float4 a = *(const float4*)&A[(size_t)(row0 + ar) * K + k0 + ac];
            As[(ac + 0) * 64 + ar] = a.x;
            As[(ac + 1) * 64 + ar] = a.y;
            As[(ac + 2) * 64 + ar] = a.z;
            As[(ac + 3) * 64 + ar] = a.w;
        }
        if (BT) {
            int br = tid >> 2;              // n index within tile
            int bc = (tid & 3) * 4;         // k offset
            float4 b = *(const float4*)&B[(size_t)(col0 + br) * K + k0 + bc];
            Bs[(bc + 0) * 64 + br] = b.x;
            Bs[(bc + 1) * 64 + br] = b.y;
            Bs[(bc + 2) * 64 + br] = b.z;
            Bs[(bc + 3) * 64 + br] = b.w;
        } else {
            int bk = tid >> 4;              // k index within tile (0..15)
            int bn = (tid & 15) * 4;        // n offset
            float4 b = *(const float4*)&B[(size_t)(k0 + bk) * N + col0 + bn];
            *(float4*)&Bs[bk * 64 + bn] = b;
        }
        __syncthreads();

#pragma unroll
        for (int kk = 0; kk < 16; kk++) {
            float4 a4 = *(const float4*)&As[kk * 64 + ty * 4];
            float4 b4 = *(const float4*)&Bs[kk * 64 + tx * 4];
            acc[0][0] += a4.x * b4.x; acc[0][1] += a4.x * b4.y;
            acc[0][2] += a4.x * b4.z; acc[0][3] += a4.x * b4.w;
            acc[1][0] += a4.y * b4.x; acc[1][1] += a4.y * b4.y;
            acc[1][2] += a4.y * b4.z; acc[1][3] += a4.y * b4.w;
            acc[2][0] += a4.z * b4.x; acc[2][1] += a4.z * b4.y;
            acc[2][2] += a4.z * b4.z; acc[2][3] += a4.z * b4.w;
            acc[3][0] += a4.w * b4.x; acc[3][1] += a4.w * b4.y;
            acc[3][2] += a4.w * b4.z; acc[3][3] += a4.w * b4.w;
        }
        __syncthreads();
    }

    float4 bi = *(const float4*)&bias[col0 + tx * 4];
#pragma unroll
    for (int i = 0; i < 4; i++) {
        float4 v = make_float4(acc[i][0] + bi.x, acc[i][1] + bi.y,
                               acc[i][2] + bi.z, acc[i][3] + bi.w);
        if (LRELU) {
            v.x = v.x > 0.0f ? v.x : 0.2f * v.x;
            v.y = v.y > 0.0f ? v.y : 0.2f * v.y;
            v.z = v.z > 0.0f ? v.z : 0.2f * v.z;
            v.w = v.w > 0.0f ? v.w : 0.2f * v.w;
        }
        *(float4*)&C[(size_t)(row0 + ty * 4 + i) * N + col0 + tx * 4] = v;
    }
}

// ---------------- flash attention (fp32, online softmax) -------------------
// grid (E/64, H), block 256.  qkv layout [E, 768] = [q|k|v] each [E, 256].
__global__ void flash_attn_kernel(const float* __restrict__ qkv,
                                  const unsigned char* __restrict__ mask,
                                  float* __restrict__ o) {
    __shared__ float Qt[32 * 64];   // Q^T [d][q], pre-scaled
    __shared__ float Kt[32 * 64];   // K^T [d][k]
    __shared__ float Vs[64 * 32];   // V   [k][d]
    __shared__ float Pt[64 * 64];   // P^T [k][q]

    int tid = threadIdx.x;
    int tx = tid & 15;              // key/dim group
    int ty = tid >> 4;              // query group
    int q0 = blockIdx.x * 64;
    int h  = blockIdx.y;
    const float scale = 0.17677669529663687f; // 1/sqrt(32)
    int qoff = h * 32;
    int koff = 256 + h * 32;
    int voff = 512 + h * 32;

#pragma unroll
    for (int i = 0; i < 8; i++) {
        int lin = i * 256 + tid;
        int q = lin >> 5, d = lin & 31;
        Qt[d * 64 + q] = qkv[(size_t)(q0 + q) * 768 + qoff + d] * scale;
    }

    float m[4], l[4], acc[4][2];
#pragma unroll
    for (int r = 0; r < 4; r++) {
        m[r] = -1e30f; l[r] = 0.0f; acc[r][0] = 0.0f; acc[r][1] = 0.0f;
    }

    for (int kb = 0; kb < 64; kb++) {
        int k0 = kb * 64;
#pragma unroll
        for (int i = 0; i < 8; i++) {
            int lin = i * 256 + tid;
            int k = lin >> 5, d = lin & 31;
            Kt[d * 64 + k] = qkv[(size_t)(k0 + k) * 768 + koff + d];
            Vs[k * 32 + d] = qkv[(size_t)(k0 + k) * 768 + voff + d];
        }
        __syncthreads();

        float s[4][4];
#pragma unroll
        for (int r = 0; r < 4; r++)
#pragma unroll
            for (int c = 0; c < 4; c++) s[r][c] = 0.0f;

#pragma unroll
        for (int d = 0; d < 32; d++) {
            float4 a4 = *(const float4*)&Qt[d * 64 + ty * 4];
            float4 b4 = *(const float4*)&Kt[d * 64 + tx * 4];
            s[0][0] += a4.x * b4.x; s[0][1] += a4.x * b4.y;
            s[0][2] += a4.x * b4.z; s[0][3] += a4.x * b4.w;
            s[1][0] += a4.y * b4.x; s[1][1] += a4.y * b4.y;
            s[1][2] += a4.y * b4.z; s[1][3] += a4.y * b4.w;
            s[2][0] += a4.z * b4.x; s[2][1] += a4.z * b4.y;
            s[2][2] += a4.z * b4.z; s[2][3] += a4.z * b4.w;
            s[3][0] += a4.w * b4.x; s[3][1] += a4.w * b4.y;
            s[3][2] += a4.w * b4.z; s[3][3] += a4.w * b4.w;
        }

        // additive mask (canonical u8, 1 byte per element)
#pragma unroll
        for (int r = 0; r < 4; r++) {
            int qg = q0 + ty * 4 + r;
            uchar4 mm = *(const uchar4*)&mask[(size_t)qg * 4096 + k0 + tx * 4];
            if (!mm.x) s[r][0] += NEG_;
            if (!mm.y) s[r][1] += NEG_;
            if (!mm.z) s[r][2] += NEG_;
            if (!mm.w) s[r][3] += NEG_;
        }

        // online softmax
#pragma unroll
        for (int r = 0; r < 4; r++) {
            float rm = fmaxf(fmaxf(s[r][0], s[r][1]), fmaxf(s[r][2], s[r][3]));
#pragma unroll
            for (int off = 8; off; off >>= 1)
                rm = fmaxf(rm, __shfl_xor_sync(0xffffffffu, rm, off, 16));
            float mn = fmaxf(m[r], rm);
            float corr = __expf(m[r] - mn);
            m[r] = mn;
            float ps = 0.0f;
#pragma unroll
            for (int c = 0; c < 4; c++) {
                float p = __expf(s[r][c] - mn);
                Pt[(tx * 4 + c) * 64 + ty * 4 + r] = p;
                ps += p;
            }
#pragma unroll
            for (int off = 8; off; off >>= 1)
                ps += __shfl_xor_sync(0xffffffffu, ps, off, 16);
            l[r] = l[r] * corr + ps;
            acc[r][0] *= corr;
            acc[r][1] *= corr;
        }
        __syncthreads();

        // PV: acc[r][d2] += sum_k P[r,k] * V[k, 2tx + d2]
#pragma unroll 4
        for (int k = 0; k < 64; k++) {
            float4 p4 = *(const float4*)&Pt[k * 64 + ty * 4];
            float2 v2 = *(const float2*)&Vs[k * 32 + tx * 2];
            acc[0][0] += p4.x * v2.x; acc[0][1] += p4.x * v2.y;
            acc[1][0] += p4.y * v2.x; acc[1][1] += p4.y * v2.y;
            acc[2][0] += p4.z * v2.x; acc[2][1] += p4.z * v2.y;
            acc[3][0] += p4.w * v2.x; acc[3][1] += p4.w * v2.y;
        }
        __syncthreads();
    }

#pragma unroll
    for (int r = 0; r < 4; r++) {
        float inv = 1.0f / l[r];
        int qg = q0 + ty * 4 + r;
        float2 res = make_float2(acc[r][0] * inv, acc[r][1] * inv);
        *(float2*)&o[(size_t)qg * 256 + h * 32 + tx * 2] = res;
    }
}

// ---------------- scatter-add into node buffer ------------------------------
__global__ void scatter_add_kernel(const float* __restrict__ msg,
                                   const int* __restrict__ ei,
                                   float* __restrict__ node) {
    int e = blockIdx.x;
    int d = threadIdx.x;
    int t = ei[E_ + e];
    atomicAdd(&node[(size_t)t * 256 + d], msg[(size_t)e * 256 + d]);
}

// ---------------- layernorm helpers ----------------------------------------
__device__ __forceinline__ float block_sum256(float v, float* sbuf) {
#pragma unroll
    for (int off = 16; off; off >>= 1) v += __shfl_xor_sync(0xffffffffu, v, off);
    int w = threadIdx.x >> 5;
    if ((threadIdx.x & 31) == 0) sbuf[w] = v;
    __syncthreads();
    if (threadIdx.x < 8) {
        float t = sbuf[threadIdx.x];
#pragma unroll
        for (int off = 4; off; off >>= 1) t += __shfl_xor_sync(0xffu, t, off);
        if (threadIdx.x == 0) sbuf[0] = t;
    }
    __syncthreads();
    float r = sbuf[0];
    __syncthreads();
    return r;
}

__global__ void ln_kernel(const float* __restrict__ in,
                          const float* __restrict__ g,
                          const float* __restrict__ b,
                          float* __restrict__ out) {
    __shared__ float sbuf[8];
    int row = blockIdx.x, t = threadIdx.x;
    float v = in[(size_t)row * 256 + t];
    float mu = block_sum256(v, sbuf) * (1.0f / 256.0f);
    float dv = v - mu;
    float var = block_sum256(dv * dv, sbuf) * (1.0f / 256.0f);
    out[(size_t)row * 256 + t] = dv * rsqrtf(var + 1e-5f) * g[t] + b[t];
}

__global__ void ln_add_kernel(const float* __restrict__ in1,
                              const float* __restrict__ in2,
                              const float* __restrict__ g,
                              const float* __restrict__ b,
                              float* __restrict__ out) {
    __shared__ float sbuf[8];
    int row = blockIdx.x, t = threadIdx.x;
    float v = in1[(size_t)row * 256 + t] + in2[(size_t)row * 256 + t];
    float mu = block_sum256(v, sbuf) * (1.0f / 256.0f);
    float dv = v - mu;
    float var = block_sum256(dv * dv, sbuf) * (1.0f / 256.0f);
    out[(size_t)row * 256 + t] = dv * rsqrtf(var + 1e-5f) * g[t] + b[t];
}

// ---------------- launch ----------------------------------------------------
extern "C" void kernel_launch(void* const* d_in, const int* in_sizes, int n_in,
                              void* d_out, int out_size) {
    const float* x    = (const float*)d_in[0];
    const int*   ei   = (const int*)d_in[1];
    const float* ea   = (const float*)d_in[2];
    const unsigned int* mask_raw = (const unsigned int*)d_in[3];
    const float* W1   = (const float*)d_in[4];
    const float* b1   = (const float*)d_in[5];
    const float* W2   = (const float*)d_in[6];
    const float* b2   = (const float*)d_in[7];
    const float* ipw  = (const float*)d_in[8];
    const float* ipb  = (const float*)d_in[9];
    const float* ow   = (const float*)d_in[10];
    const float* ob   = (const float*)d_in[11];
    const float* root = (const float*)d_in[12];
    const float* bp   = (const float*)d_in[13];
    const float* l1g  = (const float*)d_in[14];
    const float* l1b  = (const float*)d_in[15];
    const float* l2g  = (const float*)d_in[16];
    const float* l2b  = (const float*)d_in[17];
    const float* lw   = (const float*)d_in[18];
    const float* lb   = (const float*)d_in[19];
    float* out = (float*)d_out;

    float *cat, *h1, *h, *qkv, *o, *msg, *node, *y, *z;
    unsigned char* mb;
    cudaGetSymbolAddress((void**)&cat,  g_cat);
    cudaGetSymbolAddress((void**)&h1,   g_h1);
    cudaGetSymbolAddress((void**)&h,    g_h);
    cudaGetSymbolAddress((void**)&qkv,  g_qkv);
    cudaGetSymbolAddress((void**)&o,    g_o);
    cudaGetSymbolAddress((void**)&msg,  g_msg);
    cudaGetSymbolAddress((void**)&node, g_node);
    cudaGetSymbolAddress((void**)&y,    g_y);
    cudaGetSymbolAddress((void**)&z,    g_z);
    cudaGetSymbolAddress((void**)&mb,   g_mask);

    // canonicalize mask (format auto-detected from data)
    mask_convert_kernel<<<(E_ * E_) / (256 * 4), 256>>>(mask_raw, mb);

    gather_cat_kernel<<<E_, 256>>>(x, ei, ea, cat);

    // h1 = leakyrelu(cat @ W1^T + b1)   [4096,768]x[256,768]^T
    sgemm_kernel<true, true ><<<dim3(4, 64), 256>>>(cat, W1, b1, h1, E_, 256, 768);
    // h = h1 @ W2^T + b2
    sgemm_kernel<true, false><<<dim3(4, 64), 256>>>(h1, W2, b2, h, E_, 256, 256);
    // qkv = h @ in_proj_w^T + in_proj_b   [4096,256]x[768,256]^T
    sgemm_kernel<true, false><<<dim3(12, 64), 256>>>(h, ipw, ipb, qkv, E_, 768, 256);

    flash_attn_kernel<<<dim3(64, 8), 256>>>(qkv, mb, o);

    // msg = o @ out_w^T + out_b
    sgemm_kernel<true, false><<<dim3(4, 64), 256>>>(o, ow, ob, msg, E_, 256, 256);
    // node = x @ root + bias_p   (B stored [K,N])
    sgemm_kernel<false, false><<<dim3(4, 32), 256>>>(x, root, bp, node, NN_, 256, 256);

    scatter_add_kernel<<<E_, 256>>>(msg, ei, node);

    ln_kernel<<<NN_, 256>>>(node, l1g, l1b, y);
    // z = y @ lin_w^T + lin_b
    sgemm_kernel<true, false><<<dim3(4, 32), 256>>>(y, lw, lb, z, NN_, 256, 256);
    ln_add_kernel<<<NN_, 256>>>(y, z, l2g, l2b, out);
}

// round 3
// speedup vs baseline: 3.0095x; 3.0095x over previous
#include <cuda_runtime.h>

#define E_    4096
#define NN_   2048
#define D_    256
#define H_    8
#define DH_   32
#define NEG_  (-10000.0f)

// ---------------- scratch (device globals; no allocation allowed) ----------
__device__ float g_cat [E_ * 3 * D_];
__device__ float g_h1  [E_ * D_];
__device__ float g_h   [E_ * D_];
__device__ float g_qkv [E_ * 3 * D_];
__device__ float g_o   [E_ * D_];
__device__ float g_msg [E_ * D_];
__device__ float g_node[NN_ * D_];
__device__ float g_y   [NN_ * D_];
__device__ float g_z   [NN_ * D_];
__device__ unsigned char g_mask[(size_t)E_ * E_];   // canonical u8 mask

// ---------------- tf32 helpers ----------------------------------------------
__device__ __forceinline__ unsigned f2tf32(float f) {
    unsigned u;
    asm("cvt.rna.tf32.f32 %0, %1;" : "=r"(u) : "f"(f));
    return u;
}

// mma.sync m16n8k8 tf32: C(16x8,f32) += A(16x8,row) * B(8x8,col)
__device__ __forceinline__ void mma_tf32(float* c,
                                         unsigned a0, unsigned a1,
                                         unsigned a2, unsigned a3,
                                         unsigned b0, unsigned b1) {
    asm volatile(
        "mma.sync.aligned.m16n8k8.row.col.f32.tf32.tf32.f32 "
        "{%0,%1,%2,%3}, {%4,%5,%6,%7}, {%8,%9}, {%0,%1,%2,%3};\n"
        : "+f"(c[0]), "+f"(c[1]), "+f"(c[2]), "+f"(c[3])
        : "r"(a0), "r"(a1), "r"(a2), "r"(a3), "r"(b0), "r"(b1));
}

// ---------------- mask canonicalization ------------------------------------
__global__ void mask_convert_kernel(const unsigned int* __restrict__ mw,
                                    unsigned char* __restrict__ mb) {
    __shared__ int cnt[4];
    if (threadIdx.x < 4) cnt[threadIdx.x] = 0;
    __syncthreads();
    if (threadIdx.x < 64) {
        unsigned int w = mw[threadIdx.x];
        if      (w == 0x01010101u) atomicAdd(&cnt[0], 1);  // u8 bool
        else if (w == 0x3F800000u) atomicAdd(&cnt[1], 1);  // float32
        else if (w == 0x00000001u) atomicAdd(&cnt[2], 1);  // int32
        else if (w == 0x3F803F80u) atomicAdd(&cnt[3], 1);  // bf16
    }
    __syncthreads();
    int fmt = 0, best = cnt[0];
    if (cnt[1] > best) { best = cnt[1]; fmt = 1; }
    if (cnt[2] > best) { best = cnt[2]; fmt = 2; }
    if (cnt[3] > best) { best = cnt[3]; fmt = 3; }

    size_t idx = ((size_t)blockIdx.x * blockDim.x + threadIdx.x) * 4;
    uchar4 outv;
    if (fmt == 0) {
        uchar4 v = *(const uchar4*)((const unsigned char*)mw + idx);
        outv = make_uchar4(v.x != 0, v.y != 0, v.z != 0, v.w != 0);
    } else if (fmt == 1 || fmt == 2) {
        uint4 v = *(const uint4*)(mw + idx);
        outv = make_uchar4(v.x != 0, v.y != 0, v.z != 0, v.w != 0);
    } else {
        const unsigned short* ms = (const unsigned short*)mw;
        outv = make_uchar4(ms[idx] != 0, ms[idx + 1] != 0,
                           ms[idx + 2] != 0, ms[idx + 3] != 0);
    }
    *(uchar4*)&mb[idx] = outv;
}

// ---------------- gather: cat = [x_i, x_j, edge_attr] ----------------------
__global__ void gather_cat_kernel(const float* __restrict__ x,
                                  const int* __restrict__ ei,
                                  const float* __restrict__ ea,
                                  float* __restrict__ cat) {
    int e = blockIdx.x;
    int d = threadIdx.x;
    int src = ei[e];
    int tgt = ei[E_ + e];
    cat[(size_t)e * 768 + d]       = x[(size_t)tgt * 256 + d];
    cat[(size_t)e * 768 + 256 + d] = x[(size_t)src * 256 + d];
    cat[(size_t)e * 768 + 512 + d] = ea[(size_t)e * 256 + d];
}

// ---------------- tf32 tensor-core GEMM -------------------------------------
// C[M,N] = A[M,K] @ op(B) + bias.  BT: B stored [N,K]; !BT: B stored [K,N].
// Block: 128 threads (4 warps). Tile M=64 (16/warp), N=64, K-step 32.
template <bool BT, bool LRELU>
__global__ void mma_gemm_kernel(const float* __restrict__ A,
                                const float* __restrict__ B,
                                const float* __restrict__ bias,
                                float* __restrict__ C,
                                int M, int N, int K) {
    __shared__ unsigned As[64][36];   // [m][k] tf32 bits
    __shared__ unsigned Bs[64][36];   // [n][k] tf32 bits

    int tid  = threadIdx.x;
    int warp = tid >> 5, lane = tid & 31;
    int g = lane >> 2, ti = lane & 3;
    int row0 = blockIdx.y * 64;
    int col0 = blockIdx.x * 64;

    float acc[8][4];
#pragma unroll
    for (int n = 0; n < 8; n++)
#pragma unroll
        for (int j = 0; j < 4; j++) acc[n][j] = 0.0f;

    for (int k0 = 0; k0 < K; k0 += 32) {
        __syncthreads();
#pragma unroll
        for (int i = 0; i < 16; i++) {
            int lin = i * 128 + tid;
            int r = lin >> 5, c = lin & 31;
            As[r][c] = f2tf32(A[(size_t)(row0 + r) * K + k0 + c]);
        }
        if (BT) {
#pragma unroll
            for (int i = 0; i < 16; i++) {
                int lin = i * 128 + tid;
                int r = lin >> 5, c = lin & 31;
                Bs[r][c] = f2tf32(B[(size_t)(col0 + r) * K + k0 + c]);
            }
        } else {
#pragma unroll
            for (int i = 0; i < 16; i++) {
                int lin = i * 128 + tid;
                int n = lin & 63, k = lin >> 6;
                Bs[n][k] = f2tf32(B[(size_t)(k0 + k) * N + col0 + n]);
            }
        }
        __syncthreads();

#pragma unroll
        for (int ks = 0; ks < 4; ks++) {
            unsigned a0 = As[warp * 16 + g][ks * 8 + ti];
            unsigned a1 = As[warp * 16 + g + 8][ks * 8 + ti];
            unsigned a2 = As[warp * 16 + g][ks * 8 + ti + 4];
            unsigned a3 = As[warp * 16 + g + 8][ks * 8 + ti + 4];
#pragma unroll
            for (int n = 0; n < 8; n++) {
                unsigned b0 = Bs[n * 8 + g][ks * 8 + ti];
                unsigned b1 = Bs[n * 8 + g][ks * 8 + ti + 4];
                mma_tf32(acc[n], a0, a1, a2, a3, b0, b1);
            }
        }
    }

#pragma unroll
    for (int n = 0; n < 8; n++) {
        int col = col0 + n * 8 + 2 * ti;
        float bx = bias[col], by = bias[col + 1];
        float v0 = acc[n][0] + bx, v1 = acc[n][1] + by;
        float v2 = acc[n][2] + bx, v3 = acc[n][3] + by;
        if (LRELU) {
            v0 = v0 > 0.0f ? v0 : 0.2f * v0;
            v1 = v1 > 0.0f ? v1 : 0.2f * v1;
            v2 = v2 > 0.0f ? v2 : 0.2f * v2;
            v3 = v3 > 0.0f ? v3 : 0.2f * v3;
        }
        *(float2*)&C[(size_t)(row0 + warp * 16 + g) * N + col]     = make_float2(v0, v1);
        *(float2*)&C[(size_t)(row0 + warp * 16 + g + 8) * N + col] = make_float2(v2, v3);
    }
}

// ---------------- flash attention (tf32 mma, online softmax) ----------------
// grid (E/64, H), block 128 (4 warps). Each warp: 16 queries x all keys.
__global__ void flash_attn_mma_kernel(const float* __restrict__ qkv,
                                      const unsigned char* __restrict__ mask,
                                      float* __restrict__ o) {
    __shared__ unsigned Qs[64][36];       // [q][dh] tf32, pre-scaled
    __shared__ unsigned Ks[64][36];       // [key][dh] tf32
    __shared__ unsigned Vs[64][36];       // [key][dh] tf32
    __shared__ unsigned Ps[4][16][68];    // per-warp P [q][key] tf32

    int tid  = threadIdx.x;
    int warp = tid >> 5, lane = tid & 31;
    int g = lane >> 2, ti = lane & 3;
    int q0 = blockIdx.x * 64;
    int h  = blockIdx.y;
    const float scale = 0.17677669529663687f;  // 1/sqrt(32)

#pragma unroll
    for (int i = 0; i < 16; i++) {
        int lin = i * 128 + tid;
        int q = lin >> 5, d = lin & 31;
        Qs[q][d] = f2tf32(qkv[(size_t)(q0 + q) * 768 + h * 32 + d] * scale);
    }
    __syncthreads();

    int qrow = warp * 16;
    unsigned qa[4][4];
#pragma unroll
    for (int ks = 0; ks < 4; ks++) {
        qa[ks][0] = Qs[qrow + g][ks * 8 + ti];
        qa[ks][1] = Qs[qrow + g + 8][ks * 8 + ti];
        qa[ks][2] = Qs[qrow + g][ks * 8 + ti + 4];
        qa[ks][3] = Qs[qrow + g + 8][ks * 8 + ti + 4];
    }

    float m0 = -1e30f, m1 = -1e30f, l0 = 0.0f, l1 = 0.0f;
    float oacc[4][4];
#pragma unroll
    for (int n = 0; n < 4; n++)
#pragma unroll
        for (int j = 0; j < 4; j++) oacc[n][j] = 0.0f;

    size_t mrow0 = (size_t)(q0 + qrow + g) * 4096;

    for (int kb = 0; kb < 64; kb++) {
        int kk0 = kb * 64;
        __syncthreads();   // previous tile fully consumed
#pragma unroll
        for (int i = 0; i < 16; i++) {
            int lin = i * 128 + tid;
            int k = lin >> 5, d = lin & 31;
            const float* base = &qkv[(size_t)(kk0 + k) * 768 + h * 32 + d];
            Ks[k][d] = f2tf32(base[256]);
            Vs[k][d] = f2tf32(base[512]);
        }
        __syncthreads();

        // ---- S = Q K^T ----
        float sacc[8][4];
#pragma unroll
        for (int n = 0; n < 8; n++)
#pragma unroll
            for (int j = 0; j < 4; j++) sacc[n][j] = 0.0f;

#pragma unroll
        for (int ks = 0; ks < 4; ks++) {
#pragma unroll
            for (int n = 0; n < 8; n++) {
                unsigned b0 = Ks[n * 8 + g][ks * 8 + ti];
                unsigned b1 = Ks[n * 8 + g][ks * 8 + ti + 4];
                mma_tf32(sacc[n], qa[ks][0], qa[ks][1], qa[ks][2], qa[ks][3], b0, b1);
            }
        }

        // ---- mask ----
#pragma unroll
        for (int n = 0; n < 8; n++) {
            const unsigned char* mp = mask + mrow0 + kk0 + n * 8 + 2 * ti;
            uchar2 ma = *(const uchar2*)mp;
            uchar2 mb2 = *(const uchar2*)(mp + 8 * 4096);
            if (!ma.x)  sacc[n][0] += NEG_;
            if (!ma.y)  sacc[n][1] += NEG_;
            if (!mb2.x) sacc[n][2] += NEG_;
            if (!mb2.y) sacc[n][3] += NEG_;
        }

        // ---- online softmax (rows g and g+8 of this warp tile) ----
        float rmax0 = -1e30f, rmax1 = -1e30f;
#pragma unroll
        for (int n = 0; n < 8; n++) {
            rmax0 = fmaxf(rmax0, fmaxf(sacc[n][0], sacc[n][1]));
            rmax1 = fmaxf(rmax1, fmaxf(sacc[n][2], sacc[n][3]));
        }
#pragma unroll
        for (int off = 1; off <= 2; off <<= 1) {
            rmax0 = fmaxf(rmax0, __shfl_xor_sync(0xffffffffu, rmax0, off));
            rmax1 = fmaxf(rmax1, __shfl_xor_sync(0xffffffffu, rmax1, off));
        }
        float mn0 = fmaxf(m0, rmax0), mn1 = fmaxf(m1, rmax1);
        float corr0 = __expf(m0 - mn0), corr1 = __expf(m1 - mn1);
        m0 = mn0; m1 = mn1;

        float sum0 = 0.0f, sum1 = 0.0f;
#pragma unroll
        for (int n = 0; n < 8; n++) {
            float p0 = __expf(sacc[n][0] - mn0);
            float p1 = __expf(sacc[n][1] - mn0);
            float p2 = __expf(sacc[n][2] - mn1);
            float p3 = __expf(sacc[n][3] - mn1);
            sum0 += p0 + p1;
            sum1 += p2 + p3;
            Ps[warp][g][n * 8 + 2 * ti]         = f2tf32(p0);
            Ps[warp][g][n * 8 + 2 * ti + 1]     = f2tf32(p1);
            Ps[warp][g + 8][n * 8 + 2 * ti]     = f2tf32(p2);
            Ps[warp][g + 8][n * 8 + 2 * ti + 1] = f2tf32(p3);
        }
#pragma unroll
        for (int off = 1; off <= 2; off <<= 1) {
            sum0 += __shfl_xor_sync(0xffffffffu, sum0, off);
            sum1 += __shfl_xor_sync(0xffffffffu, sum1, off);
        }
        l0 = l0 * corr0 + sum0;
        l1 = l1 * corr1 + sum1;
#pragma unroll
        for (int n = 0; n < 4; n++) {
            oacc[n][0] *= corr0; oacc[n][1] *= corr0;
            oacc[n][2] *= corr1; oacc[n][3] *= corr1;
        }
        __syncwarp();

        // ---- O += P V ----
#pragma unroll
        for (int ks = 0; ks < 8; ks++) {
            unsigned pa0 = Ps[warp][g][ks * 8 + ti];
            unsigned pa1 = Ps[warp][g + 8][ks * 8 + ti];
            unsigned pa2 = Ps[warp][g][ks * 8 + ti + 4];
            unsigned pa3 = Ps[warp][g + 8][ks * 8 + ti + 4];
#pragma unroll
            for (int n = 0; n < 4; n++) {
                unsigned b0 = Vs[ks * 8 + ti][n * 8 + g];
                unsigned b1 = Vs[ks * 8 + ti + 4][n * 8 + g];
                mma_tf32(oacc[n], pa0, pa1, pa2, pa3, b0, b1);
            }
        }
    }

    float inv0 = 1.0f / l0, inv1 = 1.0f / l1;
#pragma unroll
    for (int n = 0; n < 4; n++) {
        int d = h * 32 + n * 8 + 2 * ti;
        *(float2*)&o[(size_t)(q0 + qrow + g) * 256 + d] =
            make_float2(oacc[n][0] * inv0, oacc[n][1] * inv0);
        *(float2*)&o[(size_t)(q0 + qrow + g + 8) * 256 + d] =
            make_float2(oacc[n][2] * inv1, oacc[n][3] * inv1);
    }
}

// ---------------- scatter-add into node buffer ------------------------------
__global__ void scatter_add_kernel(const float* __restrict__ msg,
                                   const int* __restrict__ ei,
                                   float* __restrict__ node) {
    int e = blockIdx.x;
    int d = threadIdx.x;
    int t = ei[E_ + e];
    atomicAdd(&node[(size_t)t * 256 + d], msg[(size_t)e * 256 + d]);
}

// ---------------- layernorm --------------------------------------------------
__device__ __forceinline__ float block_sum256(float v, float* sbuf) {
#pragma unroll
    for (int off = 16; off; off >>= 1) v += __shfl_xor_sync(0xffffffffu, v, off);
    int w = threadIdx.x >> 5;
    if ((threadIdx.x & 31) == 0) sbuf[w] = v;
    __syncthreads();
    if (threadIdx.x < 8) {
        float t = sbuf[threadIdx.x];
#pragma unroll
        for (int off = 4; off; off >>= 1) t += __shfl_xor_sync(0xffu, t, off);
        if (threadIdx.x == 0) sbuf[0] = t;
    }
    __syncthreads();
    float r = sbuf[0];
    __syncthreads();
    return r;
}

__global__ void ln_kernel(const float* __restrict__ in,
                          const float* __restrict__ g,
                          const float* __restrict__ b,
                          float* __restrict__ out) {
    __shared__ float sbuf[8];
    int row = blockIdx.x, t = threadIdx.x;
    float v = in[(size_t)row * 256 + t];
    float mu = block_sum256(v, sbuf) * (1.0f / 256.0f);
    float dv = v - mu;
    float var = block_sum256(dv * dv, sbuf) * (1.0f / 256.0f);
    out[(size_t)row * 256 + t] = dv * rsqrtf(var + 1e-5f) * g[t] + b[t];
}

__global__ void ln_add_kernel(const float* __restrict__ in1,
                              const float* __restrict__ in2,
                              const float* __restrict__ g,
                              const float* __restrict__ b,
                              float* __restrict__ out) {
    __shared__ float sbuf[8];
    int row = blockIdx.x, t = threadIdx.x;
    float v = in1[(size_t)row * 256 + t] + in2[(size_t)row * 256 + t];
    float mu = block_sum256(v, sbuf) * (1.0f / 256.0f);
    float dv = v - mu;
    float var = block_sum256(dv * dv, sbuf) * (1.0f / 256.0f);
    out[(size_t)row * 256 + t] = dv * rsqrtf(var + 1e-5f) * g[t] + b[t];
}

// ---------------- launch ----------------------------------------------------
extern "C" void kernel_launch(void* const* d_in, const int* in_sizes, int n_in,
                              void* d_out, int out_size) {
    const float* x    = (const float*)d_in[0];
    const int*   ei   = (const int*)d_in[1];
    const float* ea   = (const float*)d_in[2];
    const unsigned int* mask_raw = (const unsigned int*)d_in[3];
    const float* W1   = (const float*)d_in[4];
    const float* b1   = (const float*)d_in[5];
    const float* W2   = (const float*)d_in[6];
    const float* b2   = (const float*)d_in[7];
    const float* ipw  = (const float*)d_in[8];
    const float* ipb  = (const float*)d_in[9];
    const float* ow   = (const float*)d_in[10];
    const float* ob   = (const float*)d_in[11];
    const float* root = (const float*)d_in[12];
    const float* bp   = (const float*)d_in[13];
    const float* l1g  = (const float*)d_in[14];
    const float* l1b  = (const float*)d_in[15];
    const float* l2g  = (const float*)d_in[16];
    const float* l2b  = (const float*)d_in[17];
    const float* lw   = (const float*)d_in[18];
    const float* lb   = (const float*)d_in[19];
    float* out = (float*)d_out;

    float *cat, *h1, *h, *qkv, *o, *msg, *node, *y, *z;
    unsigned char* mb;
    cudaGetSymbolAddress((void**)&cat,  g_cat);
    cudaGetSymbolAddress((void**)&h1,   g_h1);
    cudaGetSymbolAddress((void**)&h,    g_h);
    cudaGetSymbolAddress((void**)&qkv,  g_qkv);
    cudaGetSymbolAddress((void**)&o,    g_o);
    cudaGetSymbolAddress((void**)&msg,  g_msg);
    cudaGetSymbolAddress((void**)&node, g_node);
    cudaGetSymbolAddress((void**)&y,    g_y);
    cudaGetSymbolAddress((void**)&z,    g_z);
    cudaGetSymbolAddress((void**)&mb,   g_mask);

    mask_convert_kernel<<<(E_ * E_) / (256 * 4), 256>>>(mask_raw, mb);

    gather_cat_kernel<<<E_, 256>>>(x, ei, ea, cat);

    // h1 = leakyrelu(cat @ W1^T + b1)
    mma_gemm_kernel<true, true ><<<dim3(4, 64), 128>>>(cat, W1, b1, h1, E_, 256, 768);
    // h = h1 @ W2^T + b2
    mma_gemm_kernel<true, false><<<dim3(4, 64), 128>>>(h1, W2, b2, h, E_, 256, 256);
    // qkv = h @ in_proj_w^T + in_proj_b
    mma_gemm_kernel<true, false><<<dim3(12, 64), 128>>>(h, ipw, ipb, qkv, E_, 768, 256);

    flash_attn_mma_kernel<<<dim3(64, 8), 128>>>(qkv, mb, o);

    // msg = o @ out_w^T + out_b
    mma_gemm_kernel<true, false><<<dim3(4, 64), 128>>>(o, ow, ob, msg, E_, 256, 256);
    // node = x @ root + bias_p
    mma_gemm_kernel<false, false><<<dim3(4, 32), 128>>>(x, root, bp, node, NN_, 256, 256);

    scatter_add_kernel<<<E_, 256>>>(msg, ei, node);

    ln_kernel<<<NN_, 256>>>(node, l1g, l1b, y);
    // z = y @ lin_w^T + lin_b
    mma_gemm_kernel<true, false><<<dim3(4, 32), 128>>>(y, lw, lb, z, NN_, 256, 256);
    ln_add_kernel<<<NN_, 256>>>(y, z, l2g, l2b, out);
}

// round 4
// speedup vs baseline: 3.4932x; 1.1607x over previous
#include <cuda_runtime.h>

#define E_    4096
#define NN_   2048
#define D_    256
#define H_    8
#define DH_   32
#define NEG_  (-10000.0f)

// ---------------- scratch (device globals; no allocation allowed) ----------
__device__ float g_cat [E_ * 3 * D_];
__device__ float g_h1  [E_ * D_];
__device__ float g_h   [E_ * D_];
__device__ float g_qkv [E_ * 3 * D_];
__device__ float g_o   [E_ * D_];
__device__ float g_msg [E_ * D_];
__device__ float g_node[NN_ * D_];
__device__ float g_y   [NN_ * D_];
__device__ float g_z   [NN_ * D_];
__device__ unsigned g_mbits[(size_t)E_ * E_ / 32];   // bit-packed mask (2MB)

// ---------------- tf32 helpers ----------------------------------------------
__device__ __forceinline__ unsigned f2tf32(float f) {
    unsigned u;
    asm("cvt.rna.tf32.f32 %0, %1;" : "=r"(u) : "f"(f));
    return u;
}

__device__ __forceinline__ void mma_tf32(float* c,
                                         unsigned a0, unsigned a1,
                                         unsigned a2, unsigned a3,
                                         unsigned b0, unsigned b1) {
    asm volatile(
        "mma.sync.aligned.m16n8k8.row.col.f32.tf32.tf32.f32 "
        "{%0,%1,%2,%3}, {%4,%5,%6,%7}, {%8,%9}, {%0,%1,%2,%3};\n"
        : "+f"(c[0]), "+f"(c[1]), "+f"(c[2]), "+f"(c[3])
        : "r"(a0), "r"(a1), "r"(a2), "r"(a3), "r"(b0), "r"(b1));
}

// ---------------- mask -> bitpack (format auto-detected) --------------------
// Transport dtype of the bool mask is unknown (u8/f32/i32/bf16); vote on the
// first 64 raw words, then pack 32 mask elements per uint32 bit word.
__global__ void mask_bits_kernel(const unsigned* __restrict__ mw,
                                 unsigned* __restrict__ mb) {
    __shared__ int cnt[4];
    if (threadIdx.x < 4) cnt[threadIdx.x] = 0;
    __syncthreads();
    if (threadIdx.x < 64) {
        unsigned w = mw[threadIdx.x];
        if      (w == 0x01010101u) atomicAdd(&cnt[0], 1);  // u8 bool
        else if (w == 0x3F800000u) atomicAdd(&cnt[1], 1);  // float32
        else if (w == 0x00000001u) atomicAdd(&cnt[2], 1);  // int32
        else if (w == 0x3F803F80u) atomicAdd(&cnt[3], 1);  // bf16
    }
    __syncthreads();
    int fmt = 0, best = cnt[0];
    if (cnt[1] > best) { best = cnt[1]; fmt = 1; }
    if (cnt[2] > best) { best = cnt[2]; fmt = 2; }
    if (cnt[3] > best) { best = cnt[3]; fmt = 3; }

    size_t w = (size_t)blockIdx.x * blockDim.x + threadIdx.x;  // word index
    unsigned bits = 0;
    if (fmt == 0) {
        const uchar4* p = (const uchar4*)((const unsigned char*)mw + w * 32);
#pragma unroll
        for (int j = 0; j < 8; j++) {
            uchar4 v = p[j];
            bits |= (unsigned)(v.x != 0) << (j * 4);
            bits |= (unsigned)(v.y != 0) << (j * 4 + 1);
            bits |= (unsigned)(v.z != 0) << (j * 4 + 2);
            bits |= (unsigned)(v.w != 0) << (j * 4 + 3);
        }
    } else if (fmt == 1 || fmt == 2) {
        const uint4* p = (const uint4*)(mw + w * 32);
#pragma unroll
        for (int j = 0; j < 8; j++) {
            uint4 v = p[j];
            bits |= (unsigned)(v.x != 0) << (j * 4);
            bits |= (unsigned)(v.y != 0) << (j * 4 + 1);
            bits |= (unsigned)(v.z != 0) << (j * 4 + 2);
            bits |= (unsigned)(v.w != 0) << (j * 4 + 3);
        }
    } else {
        const ushort4* p = (const ushort4*)((const unsigned short*)mw + w * 32);
#pragma unroll
        for (int j = 0; j < 8; j++) {
            ushort4 v = p[j];
            bits |= (unsigned)(v.x != 0) << (j * 4);
            bits |= (unsigned)(v.y != 0) << (j * 4 + 1);
            bits |= (unsigned)(v.z != 0) << (j * 4 + 2);
            bits |= (unsigned)(v.w != 0) << (j * 4 + 3);
        }
    }
    mb[w] = bits;
}

// ---------------- gather: cat = [x_i, x_j, edge_attr] (float4) -------------
__global__ void gather_cat_kernel(const float* __restrict__ x,
                                  const int* __restrict__ ei,
                                  const float* __restrict__ ea,
                                  float* __restrict__ cat) {
    int e = blockIdx.x;
    int t = threadIdx.x;
    int sec = t >> 6, i = (t & 63) << 2;
    const float* src;
    if (sec == 0)      src = x  + (size_t)ei[E_ + e] * 256;  // x_i (target)
    else if (sec == 1) src = x  + (size_t)ei[e] * 256;       // x_j (source)
    else               src = ea + (size_t)e * 256;
    *(float4*)&cat[(size_t)e * 768 + sec * 256 + i] = *(const float4*)&src[i];
}

// ---------------- tf32 tensor-core GEMM (float4 + reg double-buffer) -------
// C[M,N] = A[M,K] @ op(B) + bias.  BT: B stored [N,K]; !BT: B stored [K,N].
// 128 threads (4 warps), tile 64x64, K-step 32.
template <bool BT, bool LRELU>
__global__ void __launch_bounds__(128)
mma_gemm_kernel(const float* __restrict__ A,
                const float* __restrict__ B,
                const float* __restrict__ bias,
                float* __restrict__ C,
                int M, int N, int K) {
    __shared__ unsigned As[64][36];
    __shared__ unsigned Bs[64][36];

    int tid  = threadIdx.x;
    int warp = tid >> 5, lane = tid & 31;
    int g = lane >> 2, ti = lane & 3;
    int row0 = blockIdx.y * 64;
    int col0 = blockIdx.x * 64;

    float acc[8][4];
#pragma unroll
    for (int n = 0; n < 8; n++)
#pragma unroll
        for (int j = 0; j < 4; j++) acc[n][j] = 0.0f;

    float4 pa[4], pb[4];

    // prefetch tile 0
#pragma unroll
    for (int i = 0; i < 4; i++) {
        int lin = i * 128 + tid;
        int r = lin >> 3, c = (lin & 7) << 2;
        pa[i] = *(const float4*)&A[(size_t)(row0 + r) * K + c];
        if (BT) pb[i] = *(const float4*)&B[(size_t)(col0 + r) * K + c];
    }
    if (!BT) {
#pragma unroll
        for (int i = 0; i < 4; i++) {
            int lin = i * 128 + tid;
            int k = lin >> 4, c = (lin & 15) << 2;
            pb[i] = *(const float4*)&B[(size_t)k * N + col0 + c];
        }
    }

    for (int k0 = 0; k0 < K; k0 += 32) {
        // store prefetched tile to smem (tf32 bits)
#pragma unroll
        for (int i = 0; i < 4; i++) {
            int lin = i * 128 + tid;
            int r = lin >> 3, c = (lin & 7) << 2;
            As[r][c]     = f2tf32(pa[i].x);
            As[r][c + 1] = f2tf32(pa[i].y);
            As[r][c + 2] = f2tf32(pa[i].z);
            As[r][c + 3] = f2tf32(pa[i].w);
            if (BT) {
                Bs[r][c]     = f2tf32(pb[i].x);
                Bs[r][c + 1] = f2tf32(pb[i].y);
                Bs[r][c + 2] = f2tf32(pb[i].z);
                Bs[r][c + 3] = f2tf32(pb[i].w);
            }
        }
        if (!BT) {
#pragma unroll
            for (int i = 0; i < 4; i++) {
                int lin = i * 128 + tid;
                int k = lin >> 4, c = (lin & 15) << 2;
                Bs[c][k]     = f2tf32(pb[i].x);
                Bs[c + 1][k] = f2tf32(pb[i].y);
                Bs[c + 2][k] = f2tf32(pb[i].z);
                Bs[c + 3][k] = f2tf32(pb[i].w);
            }
        }
        __syncthreads();

        // prefetch next tile (overlaps with mma)
        if (k0 + 32 < K) {
            int kn = k0 + 32;
#pragma unroll
            for (int i = 0; i < 4; i++) {
                int lin = i * 128 + tid;
                int r = lin >> 3, c = (lin & 7) << 2;
                pa[i] = *(const float4*)&A[(size_t)(row0 + r) * K + kn + c];
                if (BT) pb[i] = *(const float4*)&B[(size_t)(col0 + r) * K + kn + c];
            }
            if (!BT) {
#pragma unroll
                for (int i = 0; i < 4; i++) {
                    int lin = i * 128 + tid;
                    int k = lin >> 4, c = (lin & 15) << 2;
                    pb[i] = *(const float4*)&B[(size_t)(kn + k) * N + col0 + c];
                }
            }
        }

#pragma unroll
        for (int ks = 0; ks < 4; ks++) {
            unsigned a0 = As[warp * 16 + g][ks * 8 + ti];
            unsigned a1 = As[warp * 16 + g + 8][ks * 8 + ti];
            unsigned a2 = As[warp * 16 + g][ks * 8 + ti + 4];
            unsigned a3 = As[warp * 16 + g + 8][ks * 8 + ti + 4];
#pragma unroll
            for (int n = 0; n < 8; n++) {
                unsigned b0 = Bs[n * 8 + g][ks * 8 + ti];
                unsigned b1 = Bs[n * 8 + g][ks * 8 + ti + 4];
                mma_tf32(acc[n], a0, a1, a2, a3, b0, b1);
            }
        }
        __syncthreads();
    }

#pragma unroll
    for (int n = 0; n < 8; n++) {
        int col = col0 + n * 8 + 2 * ti;
        float bx = bias[col], by = bias[col + 1];
        float v0 = acc[n][0] + bx, v1 = acc[n][1] + by;
        float v2 = acc[n][2] + bx, v3 = acc[n][3] + by;
        if (LRELU) {
            v0 = v0 > 0.0f ? v0 : 0.2f * v0;
            v1 = v1 > 0.0f ? v1 : 0.2f * v1;
            v2 = v2 > 0.0f ? v2 : 0.2f * v2;
            v3 = v3 > 0.0f ? v3 : 0.2f * v3;
        }
        *(float2*)&C[(size_t)(row0 + warp * 16 + g) * N + col]     = make_float2(v0, v1);
        *(float2*)&C[(size_t)(row0 + warp * 16 + g + 8) * N + col] = make_float2(v2, v3);
    }
}

// ---------------- flash attention (tf32 mma + bitmask + prefetch) ----------
// grid (E/64, H), block 128 (4 warps). Each warp: 16 queries x all keys.
__global__ void __launch_bounds__(128)
flash_attn_mma_kernel(const float* __restrict__ qkv,
                      const unsigned* __restrict__ mbits,
                      float* __restrict__ o) {
    __shared__ unsigned Qs[64][36];
    __shared__ unsigned Ks[64][36];
    __shared__ unsigned Vs[64][36];
    __shared__ unsigned Ps[4][16][68];

    int tid  = threadIdx.x;
    int warp = tid >> 5, lane = tid & 31;
    int g = lane >> 2, ti = lane & 3;
    int q0 = blockIdx.x * 64;
    int h  = blockIdx.y;
    const float scale = 0.17677669529663687f;  // 1/sqrt(32)

    // load Q (float4, pre-scaled)
#pragma unroll
    for (int i = 0; i < 4; i++) {
        int lin = i * 128 + tid;
        int r = lin >> 3, c = (lin & 7) << 2;
        float4 v = *(const float4*)&qkv[(size_t)(q0 + r) * 768 + h * 32 + c];
        Qs[r][c]     = f2tf32(v.x * scale);
        Qs[r][c + 1] = f2tf32(v.y * scale);
        Qs[r][c + 2] = f2tf32(v.z * scale);
        Qs[r][c + 3] = f2tf32(v.w * scale);
    }

    // prefetch K/V tile 0 into regs
    float4 kp[4], vp[4];
#pragma unroll
    for (int i = 0; i < 4; i++) {
        int lin = i * 128 + tid;
        int r = lin >> 3, c = (lin & 7) << 2;
        const float* base = &qkv[(size_t)r * 768 + h * 32 + c];
        kp[i] = *(const float4*)&base[256];
        vp[i] = *(const float4*)&base[512];
    }
    __syncthreads();

    int qrow = warp * 16;
    unsigned qa[4][4];
#pragma unroll
    for (int ks = 0; ks < 4; ks++) {
        qa[ks][0] = Qs[qrow + g][ks * 8 + ti];
        qa[ks][1] = Qs[qrow + g + 8][ks * 8 + ti];
        qa[ks][2] = Qs[qrow + g][ks * 8 + ti + 4];
        qa[ks][3] = Qs[qrow + g + 8][ks * 8 + ti + 4];
    }

    float m0 = -1e30f, m1 = -1e30f, l0 = 0.0f, l1 = 0.0f;
    float oacc[4][4];
#pragma unroll
    for (int n = 0; n < 4; n++)
#pragma unroll
        for (int j = 0; j < 4; j++) oacc[n][j] = 0.0f;

    const unsigned* mrow0 = mbits + (size_t)(q0 + qrow + g) * 128;
    const unsigned* mrow1 = mrow0 + 8 * 128;

    for (int kb = 0; kb < 64; kb++) {
        // store prefetched K/V tile
#pragma unroll
        for (int i = 0; i < 4; i++) {
            int lin = i * 128 + tid;
            int r = lin >> 3, c = (lin & 7) << 2;
            Ks[r][c]     = f2tf32(kp[i].x);
            Ks[r][c + 1] = f2tf32(kp[i].y);
            Ks[r][c + 2] = f2tf32(kp[i].z);
            Ks[r][c + 3] = f2tf32(kp[i].w);
            Vs[r][c]     = f2tf32(vp[i].x);
            Vs[r][c + 1] = f2tf32(vp[i].y);
            Vs[r][c + 2] = f2tf32(vp[i].z);
            Vs[r][c + 3] = f2tf32(vp[i].w);
        }
        __syncthreads();

        // prefetch next tile (overlaps QK/softmax/PV)
        if (kb < 63) {
            int kk = (kb + 1) * 64;
#pragma unroll
            for (int i = 0; i < 4; i++) {
                int lin = i * 128 + tid;
                int r = lin >> 3, c = (lin & 7) << 2;
                const float* base = &qkv[(size_t)(kk + r) * 768 + h * 32 + c];
                kp[i] = *(const float4*)&base[256];
                vp[i] = *(const float4*)&base[512];
            }
        }

        // ---- S = Q K^T ----
        float sacc[8][4];
#pragma unroll
        for (int n = 0; n < 8; n++)
#pragma unroll
            for (int j = 0; j < 4; j++) sacc[n][j] = 0.0f;

#pragma unroll
        for (int ks = 0; ks < 4; ks++) {
#pragma unroll
            for (int n = 0; n < 8; n++) {
                unsigned b0 = Ks[n * 8 + g][ks * 8 + ti];
                unsigned b1 = Ks[n * 8 + g][ks * 8 + ti + 4];
                mma_tf32(sacc[n], qa[ks][0], qa[ks][1], qa[ks][2], qa[ks][3], b0, b1);
            }
        }

        // ---- mask from bit words ----
        {
            uint2 wa = *(const uint2*)&mrow0[kb * 2];
            uint2 wb = *(const uint2*)&mrow1[kb * 2];
            unsigned long long ma = (unsigned long long)wa.x |
                                    ((unsigned long long)wa.y << 32);
            unsigned long long mbv = (unsigned long long)wb.x |
                                     ((unsigned long long)wb.y << 32);
#pragma unroll
            for (int n = 0; n < 8; n++) {
                int b = n * 8 + 2 * ti;
                if (!((ma  >> b) & 1))       sacc[n][0] += NEG_;
                if (!((ma  >> (b + 1)) & 1)) sacc[n][1] += NEG_;
                if (!((mbv >> b) & 1))       sacc[n][2] += NEG_;
                if (!((mbv >> (b + 1)) & 1)) sacc[n][3] += NEG_;
            }
        }

        // ---- online softmax ----
        float rmax0 = -1e30f, rmax1 = -1e30f;
#pragma unroll
        for (int n = 0; n < 8; n++) {
            rmax0 = fmaxf(rmax0, fmaxf(sacc[n][0], sacc[n][1]));
            rmax1 = fmaxf(rmax1, fmaxf(sacc[n][2], sacc[n][3]));
        }
#pragma unroll
        for (int off = 1; off <= 2; off <<= 1) {
            rmax0 = fmaxf(rmax0, __shfl_xor_sync(0xffffffffu, rmax0, off));
            rmax1 = fmaxf(rmax1, __shfl_xor_sync(0xffffffffu, rmax1, off));
        }
        float mn0 = fmaxf(m0, rmax0), mn1 = fmaxf(m1, rmax1);
        float corr0 = __expf(m0 - mn0), corr1 = __expf(m1 - mn1);
        m0 = mn0; m1 = mn1;

        float sum0 = 0.0f, sum1 = 0.0f;
#pragma unroll
        for (int n = 0; n < 8; n++) {
            float p0 = __expf(sacc[n][0] - mn0);
            float p1 = __expf(sacc[n][1] - mn0);
            float p2 = __expf(sacc[n][2] - mn1);
            float p3 = __expf(sacc[n][3] - mn1);
            sum0 += p0 + p1;
            sum1 += p2 + p3;
            Ps[warp][g][n * 8 + 2 * ti]         = f2tf32(p0);
            Ps[warp][g][n * 8 + 2 * ti + 1]     = f2tf32(p1);
            Ps[warp][g + 8][n * 8 + 2 * ti]     = f2tf32(p2);
            Ps[warp][g + 8][n * 8 + 2 * ti + 1] = f2tf32(p3);
        }
#pragma unroll
        for (int off = 1; off <= 2; off <<= 1) {
            sum0 += __shfl_xor_sync(0xffffffffu, sum0, off);
            sum1 += __shfl_xor_sync(0xffffffffu, sum1, off);
        }
        l0 = l0 * corr0 + sum0;
        l1 = l1 * corr1 + sum1;
#pragma unroll
        for (int n = 0; n < 4; n++) {
            oacc[n][0] *= corr0; oacc[n][1] *= corr0;
            oacc[n][2] *= corr1; oacc[n][3] *= corr1;
        }
        __syncwarp();

        // ---- O += P V ----
#pragma unroll
        for (int ks = 0; ks < 8; ks++) {
            unsigned pa0 = Ps[warp][g][ks * 8 + ti];
            unsigned pa1 = Ps[warp][g + 8][ks * 8 + ti];
            unsigned pa2 = Ps[warp][g][ks * 8 + ti + 4];
            unsigned pa3 = Ps[warp][g + 8][ks * 8 + ti + 4];
#pragma unroll
            for (int n = 0; n < 4; n++) {
                unsigned b0 = Vs[ks * 8 + ti][n * 8 + g];
                unsigned b1 = Vs[ks * 8 + ti + 4][n * 8 + g];
                mma_tf32(oacc[n], pa0, pa1, pa2, pa3, b0, b1);
            }
        }
        __syncthreads();   // Vs consumed before next store
    }

    float inv0 = 1.0f / l0, inv1 = 1.0f / l1;
#pragma unroll
    for (int n = 0; n < 4; n++) {
        int d = h * 32 + n * 8 + 2 * ti;
        *(float2*)&o[(size_t)(q0 + qrow + g) * 256 + d] =
            make_float2(oacc[n][0] * inv0, oacc[n][1] * inv0);
        *(float2*)&o[(size_t)(q0 + qrow + g + 8) * 256 + d] =
            make_float2(oacc[n][2] * inv1, oacc[n][3] * inv1);
    }
}

// ---------------- scatter-add into node buffer ------------------------------
__global__ void scatter_add_kernel(const float* __restrict__ msg,
                                   const int* __restrict__ ei,
                                   float* __restrict__ node) {
    int e = blockIdx.x;
    int d = threadIdx.x;
    int t = ei[E_ + e];
    atomicAdd(&node[(size_t)t * 256 + d], msg[(size_t)e * 256 + d]);
}

// ---------------- layernorm --------------------------------------------------
__device__ __forceinline__ float block_sum256(float v, float* sbuf) {
#pragma unroll
    for (int off = 16; off; off >>= 1) v += __shfl_xor_sync(0xffffffffu, v, off);
    int w = threadIdx.x >> 5;
    if ((threadIdx.x & 31) == 0) sbuf[w] = v;
    __syncthreads();
    if (threadIdx.x < 8) {
        float t = sbuf[threadIdx.x];
#pragma unroll
        for (int off = 4; off; off >>= 1) t += __shfl_xor_sync(0xffu, t, off);
        if (threadIdx.x == 0) sbuf[0] = t;
    }
    __syncthreads();
    float r = sbuf[0];
    __syncthreads();
    return r;
}

__global__ void ln_kernel(const float* __restrict__ in,
                          const float* __restrict__ g,
                          const float* __restrict__ b,
                          float* __restrict__ out) {
    __shared__ float sbuf[8];
    int row = blockIdx.x, t = threadIdx.x;
    float v = in[(size_t)row * 256 + t];
    float mu = block_sum256(v, sbuf) * (1.0f / 256.0f);
    float dv = v - mu;
    float var = block_sum256(dv * dv, sbuf) * (1.0f / 256.0f);
    out[(size_t)row * 256 + t] = dv * rsqrtf(var + 1e-5f) * g[t] + b[t];
}

__global__ void ln_add_kernel(const float* __restrict__ in1,
                              const float* __restrict__ in2,
                              const float* __restrict__ g,
                              const float* __restrict__ b,
                              float* __restrict__ out) {
    __shared__ float sbuf[8];
    int row = blockIdx.x, t = threadIdx.x;
    float v = in1[(size_t)row * 256 + t] + in2[(size_t)row * 256 + t];
    float mu = block_sum256(v, sbuf) * (1.0f / 256.0f);
    float dv = v - mu;
    float var = block_sum256(dv * dv, sbuf) * (1.0f / 256.0f);
    out[(size_t)row * 256 + t] = dv * rsqrtf(var + 1e-5f) * g[t] + b[t];
}

// ---------------- launch ----------------------------------------------------
extern "C" void kernel_launch(void* const* d_in, const int* in_sizes, int n_in,
                              void* d_out, int out_size) {
    const float* x    = (const float*)d_in[0];
    const int*   ei   = (const int*)d_in[1];
    const float* ea   = (const float*)d_in[2];
    const unsigned* mask_raw = (const unsigned*)d_in[3];
    const float* W1   = (const float*)d_in[4];
    const float* b1   = (const float*)d_in[5];
    const float* W2   = (const float*)d_in[6];
    const float* b2   = (const float*)d_in[7];
    const float* ipw  = (const float*)d_in[8];
    const float* ipb  = (const float*)d_in[9];
    const float* ow   = (const float*)d_in[10];
    const float* ob   = (const float*)d_in[11];
    const float* root = (const float*)d_in[12];
    const float* bp   = (const float*)d_in[13];
    const float* l1g  = (const float*)d_in[14];
    const float* l1b  = (const float*)d_in[15];
    const float* l2g  = (const float*)d_in[16];
    const float* l2b  = (const float*)d_in[17];
    const float* lw   = (const float*)d_in[18];
    const float* lb   = (const float*)d_in[19];
    float* out = (float*)d_out;

    float *cat, *h1, *h, *qkv, *o, *msg, *node, *y, *z;
    unsigned* mb;
    cudaGetSymbolAddress((void**)&cat,  g_cat);
    cudaGetSymbolAddress((void**)&h1,   g_h1);
    cudaGetSymbolAddress((void**)&h,    g_h);
    cudaGetSymbolAddress((void**)&qkv,  g_qkv);
    cudaGetSymbolAddress((void**)&o,    g_o);
    cudaGetSymbolAddress((void**)&msg,  g_msg);
    cudaGetSymbolAddress((void**)&node, g_node);
    cudaGetSymbolAddress((void**)&y,    g_y);
    cudaGetSymbolAddress((void**)&z,    g_z);
    cudaGetSymbolAddress((void**)&mb,   g_mbits);

    mask_bits_kernel<<<(E_ * E_ / 32) / 256, 256>>>(mask_raw, mb);

    gather_cat_kernel<<<E_, 192>>>(x, ei, ea, cat);

    // h1 = leakyrelu(cat @ W1^T + b1)
    mma_gemm_kernel<true, true ><<<dim3(4, 64), 128>>>(cat, W1, b1, h1, E_, 256, 768);
    // h = h1 @ W2^T + b2
    mma_gemm_kernel<true, false><<<dim3(4, 64), 128>>>(h1, W2, b2, h, E_, 256, 256);
    // qkv = h @ in_proj_w^T + in_proj_b
    mma_gemm_kernel<true, false><<<dim3(12, 64), 128>>>(h, ipw, ipb, qkv, E_, 768, 256);

    flash_attn_mma_kernel<<<dim3(64, 8), 128>>>(qkv, mb, o);

    // msg = o @ out_w^T + out_b
    mma_gemm_kernel<true, false><<<dim3(4, 64), 128>>>(o, ow, ob, msg, E_, 256, 256);
    // node = x @ root + bias_p
    mma_gemm_kernel<false, false><<<dim3(4, 32), 128>>>(x, root, bp, node, NN_, 256, 256);

    scatter_add_kernel<<<E_, 256>>>(msg, ei, node);

    ln_kernel<<<NN_, 256>>>(node, l1g, l1b, y);
    // z = y @ lin_w^T + lin_b
    mma_gemm_kernel<true, false><<<dim3(4, 32), 128>>>(y, lw, lb, z, NN_, 256, 256);
    ln_add_kernel<<<NN_, 256>>>(y, z, l2g, l2b, out);
}